// round 11
// baseline (speedup 1.0000x reference)
#include <cuda_runtime.h>
#include <cuda_bf16.h>

#define LN 5
#define CN 16
#define HN 256
#define WN 256
#define HW (HN*WN)
#define BN_EPS 1e-5f
#define INV_RATIO 1.25f   /* 1 / (0.4 * 2) */

// All loop-invariant parameters live in the constant bank -> LDCU/uniform port,
// keeping the l1tex pipe free for the bilinear gathers.
struct Consts {
    float minv[25][6];     // inverse affines, scaled translations
    float w1n[16][16];     // layer1, nb half (BN-folded)
    float w1e[16][16];     // layer1, ego half (BN-folded)
    float b1[16];
    float w2[8][16];  float b2[8];
    float w3[4][8];   float b3[4];
    float w4[4];      float b4;
    float wm[16][16]; float bm[16];
};

__constant__ Consts cc;      // read by the main kernel
__device__   Consts g_fold;  // staging: written by fold kernel, memcpy'd to cc

// ---- prologue: BN-fold + affine inversion into the staging struct ----
__global__ __launch_bounds__(256) void fold_kernel(
    const float* __restrict__ ptm,
    const float* __restrict__ w1, const float* __restrict__ b1,
    const float* __restrict__ g1, const float* __restrict__ be1,
    const float* __restrict__ rm1, const float* __restrict__ rv1,
    const float* __restrict__ w2, const float* __restrict__ b2,
    const float* __restrict__ g2, const float* __restrict__ be2,
    const float* __restrict__ rm2, const float* __restrict__ rv2,
    const float* __restrict__ w3, const float* __restrict__ b3,
    const float* __restrict__ g3, const float* __restrict__ be3,
    const float* __restrict__ rm3, const float* __restrict__ rv3,
    const float* __restrict__ w4, const float* __restrict__ b4,
    const float* __restrict__ wm, const float* __restrict__ bm)
{
    const int tid = threadIdx.x;

    // layer 1: split into nb half (cols 0..15) and ego half (cols 16..31)
    for (int idx = tid; idx < 16*32; idx += blockDim.x) {
        int o = idx >> 5, c = idx & 31;
        float v = w1[idx] * (g1[o] * rsqrtf(rv1[o] + BN_EPS));
        if (c < 16) g_fold.w1n[o][c]      = v;
        else        g_fold.w1e[o][c - 16] = v;
    }
    for (int idx = tid; idx < 8*16; idx += blockDim.x) {
        int o = idx >> 4;
        g_fold.w2[o][idx & 15] = w2[idx] * (g2[o] * rsqrtf(rv2[o] + BN_EPS));
    }
    for (int idx = tid; idx < 4*8; idx += blockDim.x) {
        int o = idx >> 3;
        g_fold.w3[o][idx & 7] = w3[idx] * (g3[o] * rsqrtf(rv3[o] + BN_EPS));
    }
    for (int idx = tid; idx < 16*16; idx += blockDim.x)
        g_fold.wm[idx >> 4][idx & 15] = wm[idx];

    if (tid < 16) {
        float sc = g1[tid] * rsqrtf(rv1[tid] + BN_EPS);
        g_fold.b1[tid] = (b1[tid] - rm1[tid]) * sc + be1[tid];
        g_fold.bm[tid] = bm[tid];
    }
    if (tid < 8) {
        float sc = g2[tid] * rsqrtf(rv2[tid] + BN_EPS);
        g_fold.b2[tid] = (b2[tid] - rm2[tid]) * sc + be2[tid];
    }
    if (tid < 4) {
        float sc = g3[tid] * rsqrtf(rv3[tid] + BN_EPS);
        g_fold.b3[tid] = (b3[tid] - rm3[tid]) * sc + be3[tid];
        g_fold.w4[tid] = w4[tid];
    }
    if (tid == 0) g_fold.b4 = b4[0];

    // analytic inverse of [[a,b,tx],[c,d,ty],[0,0,1]] for all 25 (j,i) pairs
    if (tid < 25) {
        const float* m = ptm + tid * 16;
        float a = m[0], b = m[1], tx = m[3] * INV_RATIO;
        float c = m[4], d = m[5], ty = m[7] * INV_RATIO;
        float inv = 1.0f / (a*d - b*c);
        g_fold.minv[tid][0] =  d * inv;
        g_fold.minv[tid][1] = -b * inv;
        g_fold.minv[tid][2] = (b*ty - d*tx) * inv;
        g_fold.minv[tid][3] = -c * inv;
        g_fold.minv[tid][4] =  a * inv;
        g_fold.minv[tid][5] = (c*tx - a*ty) * inv;
    }
}

// ---- main fused kernel ----
// One thread = one (i, h, w) output pixel, but CTAs cover 32x8 pixel TILES
// (not 1x256 rows): tap working set per CTA = 5j*16ch*(10 rows x 34 px x 4B)
// ~= 109KB -> fits L1 (228KB), so the ~4x intra-tile tap reuse hits L1
// (~39cyc) instead of L2 (~240cyc). Warps remain single-row -> coalescing
// of gathers and stores is unchanged.
__global__ __launch_bounds__(256, 3) void disco_fused_kernel(
    const float* __restrict__ x,     // [L,C,H,W]
    float* __restrict__ out)         // [L,C,H,W]
{
    // block -> (i, tile_y, tile_x); thread -> (ty, tx) in a 32x8 tile
    const int bi  = blockIdx.x;
    const int i   = bi >> 8;              // 256 tiles per agent
    const int rem = bi & 255;
    const int ty_tile = rem >> 3;         // 32 tile rows (8 px each)
    const int tx_tile = rem & 7;          // 8 tile cols (32 px each)
    const int tx = threadIdx.x & 31;
    const int ty = threadIdx.x >> 5;
    const int h  = ty_tile * 8  + ty;
    const int w  = tx_tile * 32 + tx;
    const int pix = (h << 8) + w;
    const float fw = (float)w, fh = (float)h;

    // ego channels x[i][:, h, w] -> j-invariant half of layer 1:
    // egoPart[o] = b1' + W1e[o]·ego   (ego regs die here)
    float egoPart[16];
    {
        float ego[16];
        const float* xi = x + (size_t)i * CN * HW + pix;
        #pragma unroll
        for (int c = 0; c < 16; c++) ego[c] = __ldg(xi + c * HW);
        #pragma unroll
        for (int o = 0; o < 16; o++) {
            float s = cc.b1[o];
            #pragma unroll
            for (int c = 0; c < 16; c++) s += cc.w1e[o][c] * ego[c];
            egoPart[o] = s;
        }
    }

    // softmax without max-tracking: logits are ReLU'd (>=0) and small for this
    // network, so exp() cannot overflow; e >= 1 so ssum >= L.
    float ssum = 0.0f;
    float acc[16];
    #pragma unroll
    for (int c = 0; c < 16; c++) acc[c] = 0.0f;

    #pragma unroll 1
    for (int j = 0; j < LN; j++) {
        // source coords via inv(T[j][i])
        const int mi = j * 5 + i;
        float sx = cc.minv[mi][0]*fw + cc.minv[mi][1]*fh + cc.minv[mi][2];
        float sy = cc.minv[mi][3]*fw + cc.minv[mi][4]*fh + cc.minv[mi][5];
        float x0f = floorf(sx), y0f = floorf(sy);
        float wx = sx - x0f,    wy = sy - y0f;
        bool vx0 = (x0f >=  0.0f) && (x0f <= 255.0f);
        bool vx1 = (x0f >= -1.0f) && (x0f <= 254.0f);
        bool vy0 = (y0f >=  0.0f) && (y0f <= 255.0f);
        bool vy1 = (y0f >= -1.0f) && (y0f <= 254.0f);
        float w00 = (vx0 && vy0) ? (1.0f - wx) * (1.0f - wy) : 0.0f;
        float w01 = (vx1 && vy0) ? wx * (1.0f - wy) : 0.0f;
        float w10 = (vx0 && vy1) ? (1.0f - wx) * wy : 0.0f;
        float w11 = (vx1 && vy1) ? wx * wy : 0.0f;
        int ix0 = (int)x0f, iy0 = (int)y0f;
        int cx0 = min(max(ix0,     0), 255);
        int cx1 = min(max(ix0 + 1, 0), 255);
        int cy0 = min(max(iy0,     0), 255);
        int cy1 = min(max(iy0 + 1, 0), 255);
        int o00 = cy0 * WN + cx0, o01 = cy0 * WN + cx1;
        int o10 = cy1 * WN + cx0, o11 = cy1 * WN + cx1;

        // bilinear sample 16 channels of x[j]
        float nb[16];
        const float* xj = x + (size_t)j * CN * HW;
        #pragma unroll
        for (int c = 0; c < 16; c++) {
            const float* bb = xj + c * HW;
            nb[c] = w00 * __ldg(bb + o00) + w01 * __ldg(bb + o01)
                  + w10 * __ldg(bb + o10) + w11 * __ldg(bb + o11);
        }

        // MLP: 32->16->8->4->1 (ego half of layer 1 precomputed)
        float h1[16];
        #pragma unroll
        for (int o = 0; o < 16; o++) {
            float s = egoPart[o];
            #pragma unroll
            for (int c = 0; c < 16; c++) s += cc.w1n[o][c] * nb[c];
            h1[o] = fmaxf(s, 0.0f);
        }
        float h2[8];
        #pragma unroll
        for (int o = 0; o < 8; o++) {
            float s = cc.b2[o];
            #pragma unroll
            for (int c = 0; c < 16; c++) s += cc.w2[o][c] * h1[c];
            h2[o] = fmaxf(s, 0.0f);
        }
        float h3[4];
        #pragma unroll
        for (int o = 0; o < 4; o++) {
            float s = cc.b3[o];
            #pragma unroll
            for (int c = 0; c < 8; c++) s += cc.w3[o][c] * h2[c];
            h3[o] = fmaxf(s, 0.0f);
        }
        float logit = cc.b4;
        #pragma unroll
        for (int c = 0; c < 4; c++) logit += cc.w4[c] * h3[c];
        logit = fmaxf(logit, 0.0f);

        // un-normalized softmax accumulate (no rescale chain)
        float e = __expf(logit);
        ssum += e;
        #pragma unroll
        for (int c = 0; c < 16; c++) acc[c] += e * nb[c];
    }

    // out = wm @ (acc/ssum) + bm  ->  (wm @ acc) * rinv + bm
    float rinv = 1.0f / ssum;
    float* op = out + (size_t)i * CN * HW + pix;
    #pragma unroll
    for (int o = 0; o < 16; o++) {
        float s = 0.0f;
        #pragma unroll
        for (int c = 0; c < 16; c++) s += cc.wm[o][c] * acc[c];
        op[o * HW] = s * rinv + cc.bm[o];
    }
}

extern "C" void kernel_launch(void* const* d_in, const int* in_sizes, int n_in,
                              void* d_out, int out_size) {
    (void)in_sizes; (void)n_in; (void)out_size;
    // metadata order: x, record_len, pairwise_t_matrix,
    // w1,b1,g1,be1,rm1,rv1, w2,b2,g2,be2,rm2,rv2, w3,b3,g3,be3,rm3,rv3, w4,b4, wm,bm
    const float* x   = (const float*)d_in[0];
    const float* ptm = (const float*)d_in[2];

    fold_kernel<<<1, 256>>>(
        ptm,
        (const float*)d_in[3],  (const float*)d_in[4],
        (const float*)d_in[5],  (const float*)d_in[6],
        (const float*)d_in[7],  (const float*)d_in[8],
        (const float*)d_in[9],  (const float*)d_in[10],
        (const float*)d_in[11], (const float*)d_in[12],
        (const float*)d_in[13], (const float*)d_in[14],
        (const float*)d_in[15], (const float*)d_in[16],
        (const float*)d_in[17], (const float*)d_in[18],
        (const float*)d_in[19], (const float*)d_in[20],
        (const float*)d_in[21], (const float*)d_in[22],
        (const float*)d_in[23], (const float*)d_in[24]);

    // stage -> constant bank (graph-capturable D2D memcpy node)
    void* foldAddr = nullptr;
    cudaGetSymbolAddress(&foldAddr, g_fold);
    cudaMemcpyToSymbolAsync(cc, foldAddr, sizeof(Consts), 0,
                            cudaMemcpyDeviceToDevice, 0);

    const int total = LN * HW;          // 327680
    const int threads = 256;
    const int blocks = (total + threads - 1) / threads;   // 1280 = 5 * 32 * 8 tiles
    disco_fused_kernel<<<blocks, threads>>>(x, (float*)d_out);
}

// round 12
// speedup vs baseline: 1.0025x; 1.0025x over previous
#include <cuda_runtime.h>
#include <cuda_bf16.h>

#define LN 5
#define CN 16
#define HN 256
#define WN 256
#define HW (HN*WN)
#define BN_EPS 1e-5f
#define INV_RATIO 1.25f   /* 1 / (0.4 * 2) */

// All loop-invariant parameters live in the constant bank -> LDCU/uniform port,
// keeping the l1tex pipe free for the bilinear gathers.
struct Consts {
    float minv[25][6];     // inverse affines, scaled translations
    float w1n[16][16];     // layer1, nb half (BN-folded)
    float w1e[16][16];     // layer1, ego half (BN-folded)
    float b1[16];
    float w2[8][16];  float b2[8];
    float w3[4][8];   float b3[4];
    float w4[4];      float b4;
    float wm[16][16]; float bm[16];
};

__constant__ Consts cc;      // read by the main kernel
__device__   Consts g_fold;  // staging: written by fold kernel, memcpy'd to cc

// ---- prologue: BN-fold + affine inversion into the staging struct ----
__global__ __launch_bounds__(256) void fold_kernel(
    const float* __restrict__ ptm,
    const float* __restrict__ w1, const float* __restrict__ b1,
    const float* __restrict__ g1, const float* __restrict__ be1,
    const float* __restrict__ rm1, const float* __restrict__ rv1,
    const float* __restrict__ w2, const float* __restrict__ b2,
    const float* __restrict__ g2, const float* __restrict__ be2,
    const float* __restrict__ rm2, const float* __restrict__ rv2,
    const float* __restrict__ w3, const float* __restrict__ b3,
    const float* __restrict__ g3, const float* __restrict__ be3,
    const float* __restrict__ rm3, const float* __restrict__ rv3,
    const float* __restrict__ w4, const float* __restrict__ b4,
    const float* __restrict__ wm, const float* __restrict__ bm)
{
    const int tid = threadIdx.x;

    // layer 1: split into nb half (cols 0..15) and ego half (cols 16..31)
    for (int idx = tid; idx < 16*32; idx += blockDim.x) {
        int o = idx >> 5, c = idx & 31;
        float v = w1[idx] * (g1[o] * rsqrtf(rv1[o] + BN_EPS));
        if (c < 16) g_fold.w1n[o][c]      = v;
        else        g_fold.w1e[o][c - 16] = v;
    }
    for (int idx = tid; idx < 8*16; idx += blockDim.x) {
        int o = idx >> 4;
        g_fold.w2[o][idx & 15] = w2[idx] * (g2[o] * rsqrtf(rv2[o] + BN_EPS));
    }
    for (int idx = tid; idx < 4*8; idx += blockDim.x) {
        int o = idx >> 3;
        g_fold.w3[o][idx & 7] = w3[idx] * (g3[o] * rsqrtf(rv3[o] + BN_EPS));
    }
    for (int idx = tid; idx < 16*16; idx += blockDim.x)
        g_fold.wm[idx >> 4][idx & 15] = wm[idx];

    if (tid < 16) {
        float sc = g1[tid] * rsqrtf(rv1[tid] + BN_EPS);
        g_fold.b1[tid] = (b1[tid] - rm1[tid]) * sc + be1[tid];
        g_fold.bm[tid] = bm[tid];
    }
    if (tid < 8) {
        float sc = g2[tid] * rsqrtf(rv2[tid] + BN_EPS);
        g_fold.b2[tid] = (b2[tid] - rm2[tid]) * sc + be2[tid];
    }
    if (tid < 4) {
        float sc = g3[tid] * rsqrtf(rv3[tid] + BN_EPS);
        g_fold.b3[tid] = (b3[tid] - rm3[tid]) * sc + be3[tid];
        g_fold.w4[tid] = w4[tid];
    }
    if (tid == 0) g_fold.b4 = b4[0];

    // analytic inverse of [[a,b,tx],[c,d,ty],[0,0,1]] for all 25 (j,i) pairs
    if (tid < 25) {
        const float* m = ptm + tid * 16;
        float a = m[0], b = m[1], tx = m[3] * INV_RATIO;
        float c = m[4], d = m[5], ty = m[7] * INV_RATIO;
        float inv = 1.0f / (a*d - b*c);
        g_fold.minv[tid][0] =  d * inv;
        g_fold.minv[tid][1] = -b * inv;
        g_fold.minv[tid][2] = (b*ty - d*tx) * inv;
        g_fold.minv[tid][3] = -c * inv;
        g_fold.minv[tid][4] =  a * inv;
        g_fold.minv[tid][5] = (c*tx - a*ty) * inv;
    }
}

// ---- main fused kernel ----
// One thread = one (i, h, w) output pixel, but CTAs cover 32x8 pixel TILES
// (not 1x256 rows): tap working set per CTA = 5j*16ch*(10 rows x 34 px x 4B)
// ~= 109KB -> fits L1 (228KB), so the ~4x intra-tile tap reuse hits L1
// (~39cyc) instead of L2 (~240cyc). Warps remain single-row -> coalescing
// of gathers and stores is unchanged.
__global__ __launch_bounds__(256, 3) void disco_fused_kernel(
    const float* __restrict__ x,     // [L,C,H,W]
    float* __restrict__ out)         // [L,C,H,W]
{
    // block -> (i, tile_y, tile_x); thread -> (ty, tx) in a 32x8 tile
    const int bi  = blockIdx.x;
    const int i   = bi >> 8;              // 256 tiles per agent
    const int rem = bi & 255;
    const int ty_tile = rem >> 3;         // 32 tile rows (8 px each)
    const int tx_tile = rem & 7;          // 8 tile cols (32 px each)
    const int tx = threadIdx.x & 31;
    const int ty = threadIdx.x >> 5;
    const int h  = ty_tile * 8  + ty;
    const int w  = tx_tile * 32 + tx;
    const int pix = (h << 8) + w;
    const float fw = (float)w, fh = (float)h;

    // ego channels x[i][:, h, w] -> j-invariant half of layer 1:
    // egoPart[o] = b1' + W1e[o]·ego   (ego regs die here)
    float egoPart[16];
    {
        float ego[16];
        const float* xi = x + (size_t)i * CN * HW + pix;
        #pragma unroll
        for (int c = 0; c < 16; c++) ego[c] = __ldg(xi + c * HW);
        #pragma unroll
        for (int o = 0; o < 16; o++) {
            float s = cc.b1[o];
            #pragma unroll
            for (int c = 0; c < 16; c++) s += cc.w1e[o][c] * ego[c];
            egoPart[o] = s;
        }
    }

    // softmax without max-tracking: logits are ReLU'd (>=0) and small for this
    // network, so exp() cannot overflow; e >= 1 so ssum >= L.
    float ssum = 0.0f;
    float acc[16];
    #pragma unroll
    for (int c = 0; c < 16; c++) acc[c] = 0.0f;

    #pragma unroll 1
    for (int j = 0; j < LN; j++) {
        // source coords via inv(T[j][i])
        const int mi = j * 5 + i;
        float sx = cc.minv[mi][0]*fw + cc.minv[mi][1]*fh + cc.minv[mi][2];
        float sy = cc.minv[mi][3]*fw + cc.minv[mi][4]*fh + cc.minv[mi][5];
        float x0f = floorf(sx), y0f = floorf(sy);
        float wx = sx - x0f,    wy = sy - y0f;
        bool vx0 = (x0f >=  0.0f) && (x0f <= 255.0f);
        bool vx1 = (x0f >= -1.0f) && (x0f <= 254.0f);
        bool vy0 = (y0f >=  0.0f) && (y0f <= 255.0f);
        bool vy1 = (y0f >= -1.0f) && (y0f <= 254.0f);
        float w00 = (vx0 && vy0) ? (1.0f - wx) * (1.0f - wy) : 0.0f;
        float w01 = (vx1 && vy0) ? wx * (1.0f - wy) : 0.0f;
        float w10 = (vx0 && vy1) ? (1.0f - wx) * wy : 0.0f;
        float w11 = (vx1 && vy1) ? wx * wy : 0.0f;
        int ix0 = (int)x0f, iy0 = (int)y0f;
        int cx0 = min(max(ix0,     0), 255);
        int cx1 = min(max(ix0 + 1, 0), 255);
        int cy0 = min(max(iy0,     0), 255);
        int cy1 = min(max(iy0 + 1, 0), 255);
        int o00 = cy0 * WN + cx0, o01 = cy0 * WN + cx1;
        int o10 = cy1 * WN + cx0, o11 = cy1 * WN + cx1;

        // bilinear sample 16 channels of x[j]
        float nb[16];
        const float* xj = x + (size_t)j * CN * HW;
        #pragma unroll
        for (int c = 0; c < 16; c++) {
            const float* bb = xj + c * HW;
            nb[c] = w00 * __ldg(bb + o00) + w01 * __ldg(bb + o01)
                  + w10 * __ldg(bb + o10) + w11 * __ldg(bb + o11);
        }

        // MLP: 32->16->8->4->1 (ego half of layer 1 precomputed)
        float h1[16];
        #pragma unroll
        for (int o = 0; o < 16; o++) {
            float s = egoPart[o];
            #pragma unroll
            for (int c = 0; c < 16; c++) s += cc.w1n[o][c] * nb[c];
            h1[o] = fmaxf(s, 0.0f);
        }
        float h2[8];
        #pragma unroll
        for (int o = 0; o < 8; o++) {
            float s = cc.b2[o];
            #pragma unroll
            for (int c = 0; c < 16; c++) s += cc.w2[o][c] * h1[c];
            h2[o] = fmaxf(s, 0.0f);
        }
        float h3[4];
        #pragma unroll
        for (int o = 0; o < 4; o++) {
            float s = cc.b3[o];
            #pragma unroll
            for (int c = 0; c < 8; c++) s += cc.w3[o][c] * h2[c];
            h3[o] = fmaxf(s, 0.0f);
        }
        float logit = cc.b4;
        #pragma unroll
        for (int c = 0; c < 4; c++) logit += cc.w4[c] * h3[c];
        logit = fmaxf(logit, 0.0f);

        // un-normalized softmax accumulate (no rescale chain)
        float e = __expf(logit);
        ssum += e;
        #pragma unroll
        for (int c = 0; c < 16; c++) acc[c] += e * nb[c];
    }

    // out = wm @ (acc/ssum) + bm  ->  (wm @ acc) * rinv + bm
    float rinv = 1.0f / ssum;
    float* op = out + (size_t)i * CN * HW + pix;
    #pragma unroll
    for (int o = 0; o < 16; o++) {
        float s = 0.0f;
        #pragma unroll
        for (int c = 0; c < 16; c++) s += cc.wm[o][c] * acc[c];
        op[o * HW] = s * rinv + cc.bm[o];
    }
}

extern "C" void kernel_launch(void* const* d_in, const int* in_sizes, int n_in,
                              void* d_out, int out_size) {
    (void)in_sizes; (void)n_in; (void)out_size;
    // metadata order: x, record_len, pairwise_t_matrix,
    // w1,b1,g1,be1,rm1,rv1, w2,b2,g2,be2,rm2,rv2, w3,b3,g3,be3,rm3,rv3, w4,b4, wm,bm
    const float* x   = (const float*)d_in[0];
    const float* ptm = (const float*)d_in[2];

    fold_kernel<<<1, 256>>>(
        ptm,
        (const float*)d_in[3],  (const float*)d_in[4],
        (const float*)d_in[5],  (const float*)d_in[6],
        (const float*)d_in[7],  (const float*)d_in[8],
        (const float*)d_in[9],  (const float*)d_in[10],
        (const float*)d_in[11], (const float*)d_in[12],
        (const float*)d_in[13], (const float*)d_in[14],
        (const float*)d_in[15], (const float*)d_in[16],
        (const float*)d_in[17], (const float*)d_in[18],
        (const float*)d_in[19], (const float*)d_in[20],
        (const float*)d_in[21], (const float*)d_in[22],
        (const float*)d_in[23], (const float*)d_in[24]);

    // stage -> constant bank (graph-capturable D2D memcpy node)
    void* foldAddr = nullptr;
    cudaGetSymbolAddress(&foldAddr, g_fold);
    cudaMemcpyToSymbolAsync(cc, foldAddr, sizeof(Consts), 0,
                            cudaMemcpyDeviceToDevice, 0);

    const int total = LN * HW;          // 327680
    const int threads = 256;
    const int blocks = (total + threads - 1) / threads;   // 1280 = 5 * 32 * 8 tiles
    disco_fused_kernel<<<blocks, threads>>>(x, (float*)d_out);
}

// round 13
// speedup vs baseline: 1.0710x; 1.0683x over previous
#include <cuda_runtime.h>
#include <cuda_bf16.h>

#define LN 5
#define CN 16
#define HN 256
#define WN 256
#define HW (HN*WN)
#define BN_EPS 1e-5f
#define INV_RATIO 1.25f   /* 1 / (0.4 * 2) */

// All loop-invariant parameters live in the constant bank -> LDCU/uniform port,
// keeping the l1tex pipe free for the bilinear gathers.
struct Consts {
    float minv[25][6];     // inverse affines, scaled translations
    float w1n[16][16];     // layer1, nb half (BN-folded)
    float w1e[16][16];     // layer1, ego half (BN-folded)
    float b1[16];
    float w2[8][16];  float b2[8];
    float w3[4][8];   float b3[4];
    float w4[4];      float b4;
    float wm[16][16]; float bm[16];
};

__constant__ Consts cc;      // read by the main kernel
__device__   Consts g_fold;  // staging: written by fold kernel, memcpy'd to cc

// ---- prologue: BN-fold + affine inversion into the staging struct ----
__global__ __launch_bounds__(256) void fold_kernel(
    const float* __restrict__ ptm,
    const float* __restrict__ w1, const float* __restrict__ b1,
    const float* __restrict__ g1, const float* __restrict__ be1,
    const float* __restrict__ rm1, const float* __restrict__ rv1,
    const float* __restrict__ w2, const float* __restrict__ b2,
    const float* __restrict__ g2, const float* __restrict__ be2,
    const float* __restrict__ rm2, const float* __restrict__ rv2,
    const float* __restrict__ w3, const float* __restrict__ b3,
    const float* __restrict__ g3, const float* __restrict__ be3,
    const float* __restrict__ rm3, const float* __restrict__ rv3,
    const float* __restrict__ w4, const float* __restrict__ b4,
    const float* __restrict__ wm, const float* __restrict__ bm)
{
    const int tid = threadIdx.x;

    // layer 1: split into nb half (cols 0..15) and ego half (cols 16..31)
    for (int idx = tid; idx < 16*32; idx += blockDim.x) {
        int o = idx >> 5, c = idx & 31;
        float v = w1[idx] * (g1[o] * rsqrtf(rv1[o] + BN_EPS));
        if (c < 16) g_fold.w1n[o][c]      = v;
        else        g_fold.w1e[o][c - 16] = v;
    }
    for (int idx = tid; idx < 8*16; idx += blockDim.x) {
        int o = idx >> 4;
        g_fold.w2[o][idx & 15] = w2[idx] * (g2[o] * rsqrtf(rv2[o] + BN_EPS));
    }
    for (int idx = tid; idx < 4*8; idx += blockDim.x) {
        int o = idx >> 3;
        g_fold.w3[o][idx & 7] = w3[idx] * (g3[o] * rsqrtf(rv3[o] + BN_EPS));
    }
    for (int idx = tid; idx < 16*16; idx += blockDim.x)
        g_fold.wm[idx >> 4][idx & 15] = wm[idx];

    if (tid < 16) {
        float sc = g1[tid] * rsqrtf(rv1[tid] + BN_EPS);
        g_fold.b1[tid] = (b1[tid] - rm1[tid]) * sc + be1[tid];
        g_fold.bm[tid] = bm[tid];
    }
    if (tid < 8) {
        float sc = g2[tid] * rsqrtf(rv2[tid] + BN_EPS);
        g_fold.b2[tid] = (b2[tid] - rm2[tid]) * sc + be2[tid];
    }
    if (tid < 4) {
        float sc = g3[tid] * rsqrtf(rv3[tid] + BN_EPS);
        g_fold.b3[tid] = (b3[tid] - rm3[tid]) * sc + be3[tid];
        g_fold.w4[tid] = w4[tid];
    }
    if (tid == 0) g_fold.b4 = b4[0];

    // analytic inverse of [[a,b,tx],[c,d,ty],[0,0,1]] for all 25 (j,i) pairs
    if (tid < 25) {
        const float* m = ptm + tid * 16;
        float a = m[0], b = m[1], tx = m[3] * INV_RATIO;
        float c = m[4], d = m[5], ty = m[7] * INV_RATIO;
        float inv = 1.0f / (a*d - b*c);
        g_fold.minv[tid][0] =  d * inv;
        g_fold.minv[tid][1] = -b * inv;
        g_fold.minv[tid][2] = (b*ty - d*tx) * inv;
        g_fold.minv[tid][3] = -c * inv;
        g_fold.minv[tid][4] =  a * inv;
        g_fold.minv[tid][5] = (c*tx - a*ty) * inv;
    }
}

// ---- main fused kernel: one thread = one (i, h, w) output pixel ----
// Linear row mapping (R8 — best measured). egoPart lives in conflict-free
// shared memory instead of registers: 80 -> 64 regs, 4 CTAs/SM = 32 warps,
// which is what actually hides the gather latency (issue was 61.8% at 24
// warps with no saturated pipe).
__global__ __launch_bounds__(256, 4) void disco_fused_kernel(
    const float* __restrict__ x,     // [L,C,H,W]
    float* __restrict__ out)         // [L,C,H,W]
{
    // j-invariant half of layer 1, per-thread column, transposed layout:
    // thread t accesses s_ego[o][t] -> consecutive lanes, conflict-free.
    __shared__ float s_ego[16][256];

    const int tid = threadIdx.x;
    const int gid = blockIdx.x * blockDim.x + tid;
    const int i   = gid / HW;
    const int pix = gid - i * HW;
    const int h   = pix >> 8;
    const int w   = pix & 255;
    const float fw = (float)w, fh = (float)h;

    // ego channels x[i][:, h, w] -> egoPart[o] = b1' + W1e[o]·ego, into smem.
    {
        float ego[16];
        const float* xi = x + (size_t)i * CN * HW + pix;
        #pragma unroll
        for (int c = 0; c < 16; c++) ego[c] = __ldg(xi + c * HW);
        #pragma unroll
        for (int o = 0; o < 16; o++) {
            float s = cc.b1[o];
            #pragma unroll
            for (int c = 0; c < 16; c++) s += cc.w1e[o][c] * ego[c];
            s_ego[o][tid] = s;   // own column only; no __syncthreads needed
        }
    }

    // softmax without max-tracking: logits are ReLU'd (>=0) and small for this
    // network, so exp() cannot overflow; e >= 1 so ssum >= L.
    float ssum = 0.0f;
    float acc[16];
    #pragma unroll
    for (int c = 0; c < 16; c++) acc[c] = 0.0f;

    #pragma unroll 1
    for (int j = 0; j < LN; j++) {
        // source coords via inv(T[j][i])
        const int mi = j * 5 + i;
        float sx = cc.minv[mi][0]*fw + cc.minv[mi][1]*fh + cc.minv[mi][2];
        float sy = cc.minv[mi][3]*fw + cc.minv[mi][4]*fh + cc.minv[mi][5];
        float x0f = floorf(sx), y0f = floorf(sy);
        float wx = sx - x0f,    wy = sy - y0f;
        bool vx0 = (x0f >=  0.0f) && (x0f <= 255.0f);
        bool vx1 = (x0f >= -1.0f) && (x0f <= 254.0f);
        bool vy0 = (y0f >=  0.0f) && (y0f <= 255.0f);
        bool vy1 = (y0f >= -1.0f) && (y0f <= 254.0f);
        float w00 = (vx0 && vy0) ? (1.0f - wx) * (1.0f - wy) : 0.0f;
        float w01 = (vx1 && vy0) ? wx * (1.0f - wy) : 0.0f;
        float w10 = (vx0 && vy1) ? (1.0f - wx) * wy : 0.0f;
        float w11 = (vx1 && vy1) ? wx * wy : 0.0f;
        int ix0 = (int)x0f, iy0 = (int)y0f;
        int cx0 = min(max(ix0,     0), 255);
        int cx1 = min(max(ix0 + 1, 0), 255);
        int cy0 = min(max(iy0,     0), 255);
        int cy1 = min(max(iy0 + 1, 0), 255);
        int o00 = cy0 * WN + cx0, o01 = cy0 * WN + cx1;
        int o10 = cy1 * WN + cx0, o11 = cy1 * WN + cx1;

        // bilinear sample 16 channels of x[j]
        float nb[16];
        const float* xj = x + (size_t)j * CN * HW;
        #pragma unroll
        for (int c = 0; c < 16; c++) {
            const float* bb = xj + c * HW;
            nb[c] = w00 * __ldg(bb + o00) + w01 * __ldg(bb + o01)
                  + w10 * __ldg(bb + o10) + w11 * __ldg(bb + o11);
        }

        // MLP: 32->16->8->4->1 (ego half of layer 1 from smem)
        float h1[16];
        #pragma unroll
        for (int o = 0; o < 16; o++) {
            float s = s_ego[o][tid];
            #pragma unroll
            for (int c = 0; c < 16; c++) s += cc.w1n[o][c] * nb[c];
            h1[o] = fmaxf(s, 0.0f);
        }
        float h2[8];
        #pragma unroll
        for (int o = 0; o < 8; o++) {
            float s = cc.b2[o];
            #pragma unroll
            for (int c = 0; c < 16; c++) s += cc.w2[o][c] * h1[c];
            h2[o] = fmaxf(s, 0.0f);
        }
        float h3[4];
        #pragma unroll
        for (int o = 0; o < 4; o++) {
            float s = cc.b3[o];
            #pragma unroll
            for (int c = 0; c < 8; c++) s += cc.w3[o][c] * h2[c];
            h3[o] = fmaxf(s, 0.0f);
        }
        float logit = cc.b4;
        #pragma unroll
        for (int c = 0; c < 4; c++) logit += cc.w4[c] * h3[c];
        logit = fmaxf(logit, 0.0f);

        // un-normalized softmax accumulate (no rescale chain)
        float e = __expf(logit);
        ssum += e;
        #pragma unroll
        for (int c = 0; c < 16; c++) acc[c] += e * nb[c];
    }

    // out = wm @ (acc/ssum) + bm  ->  (wm @ acc) * rinv + bm
    float rinv = 1.0f / ssum;
    float* op = out + (size_t)i * CN * HW + pix;
    #pragma unroll
    for (int o = 0; o < 16; o++) {
        float s = 0.0f;
        #pragma unroll
        for (int c = 0; c < 16; c++) s += cc.wm[o][c] * acc[c];
        op[o * HW] = s * rinv + cc.bm[o];
    }
}

extern "C" void kernel_launch(void* const* d_in, const int* in_sizes, int n_in,
                              void* d_out, int out_size) {
    (void)in_sizes; (void)n_in; (void)out_size;
    // metadata order: x, record_len, pairwise_t_matrix,
    // w1,b1,g1,be1,rm1,rv1, w2,b2,g2,be2,rm2,rv2, w3,b3,g3,be3,rm3,rv3, w4,b4, wm,bm
    const float* x   = (const float*)d_in[0];
    const float* ptm = (const float*)d_in[2];

    fold_kernel<<<1, 256>>>(
        ptm,
        (const float*)d_in[3],  (const float*)d_in[4],
        (const float*)d_in[5],  (const float*)d_in[6],
        (const float*)d_in[7],  (const float*)d_in[8],
        (const float*)d_in[9],  (const float*)d_in[10],
        (const float*)d_in[11], (const float*)d_in[12],
        (const float*)d_in[13], (const float*)d_in[14],
        (const float*)d_in[15], (const float*)d_in[16],
        (const float*)d_in[17], (const float*)d_in[18],
        (const float*)d_in[19], (const float*)d_in[20],
        (const float*)d_in[21], (const float*)d_in[22],
        (const float*)d_in[23], (const float*)d_in[24]);

    // stage -> constant bank (graph-capturable D2D memcpy node)
    void* foldAddr = nullptr;
    cudaGetSymbolAddress(&foldAddr, g_fold);
    cudaMemcpyToSymbolAsync(cc, foldAddr, sizeof(Consts), 0,
                            cudaMemcpyDeviceToDevice, 0);

    const int total = LN * HW;          // 327680
    const int threads = 256;
    const int blocks = (total + threads - 1) / threads;   // 1280
    disco_fused_kernel<<<blocks, threads>>>(x, (float*)d_out);
}

// round 15
// speedup vs baseline: 1.1113x; 1.0376x over previous
#include <cuda_runtime.h>
#include <cuda_fp16.h>
#include <cuda_bf16.h>

#define LN 5
#define CN 16
#define HN 256
#define WN 256
#define HW (HN*WN)
#define BN_EPS 1e-5f
#define INV_RATIO 1.25f   /* 1 / (0.4 * 2) */

// All loop-invariant parameters live in the constant bank -> LDCU/uniform port.
struct Consts {
    float minv[25][6];     // inverse affines, scaled translations
    float w1n[16][16];     // layer1, nb half (BN-folded)
    float w1e[16][16];     // layer1, ego half (BN-folded)
    float b1[16];
    float w2[8][16];  float b2[8];
    float w3[4][8];   float b3[4];
    float w4[4];      float b4;
    float wm[16][16]; float bm[16];
};

__constant__ Consts cc;      // read by the main kernel
__device__   Consts g_fold;  // staging: written by fold kernel, memcpy'd to cc

// fp16 pixel-major repack of x: [L, H, W, C] as 2x uint4 (8 halves each) per
// pixel. One bilinear tap = 2 LDG.128 instead of 16 scattered LDG.32, and a
// 128B line covers 4 source pixels -> ~4x fewer l1tex wavefronts on gathers.
__device__ uint4 g_xp[(size_t)LN * HW * 2];   // 10.5 MB scratch

union Pack8 { uint4 u; __half2 h[4]; };

// ---- prologue 1: BN-fold + affine inversion into the staging struct ----
__global__ __launch_bounds__(256) void fold_kernel(
    const float* __restrict__ ptm,
    const float* __restrict__ w1, const float* __restrict__ b1,
    const float* __restrict__ g1, const float* __restrict__ be1,
    const float* __restrict__ rm1, const float* __restrict__ rv1,
    const float* __restrict__ w2, const float* __restrict__ b2,
    const float* __restrict__ g2, const float* __restrict__ be2,
    const float* __restrict__ rm2, const float* __restrict__ rv2,
    const float* __restrict__ w3, const float* __restrict__ b3,
    const float* __restrict__ g3, const float* __restrict__ be3,
    const float* __restrict__ rm3, const float* __restrict__ rv3,
    const float* __restrict__ w4, const float* __restrict__ b4,
    const float* __restrict__ wm, const float* __restrict__ bm)
{
    const int tid = threadIdx.x;

    for (int idx = tid; idx < 16*32; idx += blockDim.x) {
        int o = idx >> 5, c = idx & 31;
        float v = w1[idx] * (g1[o] * rsqrtf(rv1[o] + BN_EPS));
        if (c < 16) g_fold.w1n[o][c]      = v;
        else        g_fold.w1e[o][c - 16] = v;
    }
    for (int idx = tid; idx < 8*16; idx += blockDim.x) {
        int o = idx >> 4;
        g_fold.w2[o][idx & 15] = w2[idx] * (g2[o] * rsqrtf(rv2[o] + BN_EPS));
    }
    for (int idx = tid; idx < 4*8; idx += blockDim.x) {
        int o = idx >> 3;
        g_fold.w3[o][idx & 7] = w3[idx] * (g3[o] * rsqrtf(rv3[o] + BN_EPS));
    }
    for (int idx = tid; idx < 16*16; idx += blockDim.x)
        g_fold.wm[idx >> 4][idx & 15] = wm[idx];

    if (tid < 16) {
        float sc = g1[tid] * rsqrtf(rv1[tid] + BN_EPS);
        g_fold.b1[tid] = (b1[tid] - rm1[tid]) * sc + be1[tid];
        g_fold.bm[tid] = bm[tid];
    }
    if (tid < 8) {
        float sc = g2[tid] * rsqrtf(rv2[tid] + BN_EPS);
        g_fold.b2[tid] = (b2[tid] - rm2[tid]) * sc + be2[tid];
    }
    if (tid < 4) {
        float sc = g3[tid] * rsqrtf(rv3[tid] + BN_EPS);
        g_fold.b3[tid] = (b3[tid] - rm3[tid]) * sc + be3[tid];
        g_fold.w4[tid] = w4[tid];
    }
    if (tid == 0) g_fold.b4 = b4[0];

    // analytic inverse of [[a,b,tx],[c,d,ty],[0,0,1]] for all 25 (j,i) pairs
    if (tid < 25) {
        const float* m = ptm + tid * 16;
        float a = m[0], b = m[1], tx = m[3] * INV_RATIO;
        float c = m[4], d = m[5], ty = m[7] * INV_RATIO;
        float inv = 1.0f / (a*d - b*c);
        g_fold.minv[tid][0] =  d * inv;
        g_fold.minv[tid][1] = -b * inv;
        g_fold.minv[tid][2] = (b*ty - d*tx) * inv;
        g_fold.minv[tid][3] = -c * inv;
        g_fold.minv[tid][4] =  a * inv;
        g_fold.minv[tid][5] = (c*tx - a*ty) * inv;
    }
}

// ---- prologue 2: channel-major f32 -> pixel-major fp16 repack ----
// Reads coalesced (consecutive lanes, consecutive w), writes coalesced
// 32B/thread. ~31MB of traffic, a few microseconds.
__global__ __launch_bounds__(256) void repack_kernel(const float* __restrict__ x)
{
    const int gid = blockIdx.x * blockDim.x + threadIdx.x;   // over LN*HW
    const int l   = gid / HW;
    const int pix = gid - l * HW;
    const float* xi = x + (size_t)l * CN * HW + pix;

    Pack8 a, b;
    #pragma unroll
    for (int p = 0; p < 4; p++)
        a.h[p] = __floats2half2_rn(__ldg(xi + (2*p) * HW), __ldg(xi + (2*p+1) * HW));
    #pragma unroll
    for (int p = 0; p < 4; p++)
        b.h[p] = __floats2half2_rn(__ldg(xi + (8+2*p) * HW), __ldg(xi + (8+2*p+1) * HW));

    g_xp[(size_t)gid * 2 + 0] = a.u;
    g_xp[(size_t)gid * 2 + 1] = b.u;
}

__device__ __forceinline__ void tap_accum(const uint4* __restrict__ xp,
                                          int off, float wt, float* nb)
{
    Pack8 A, B;
    A.u = __ldg(xp + ((size_t)off << 1));
    B.u = __ldg(xp + ((size_t)off << 1) + 1);
    #pragma unroll
    for (int p = 0; p < 4; p++) {
        float2 v = __half22float2(A.h[p]);
        nb[2*p]   += wt * v.x;
        nb[2*p+1] += wt * v.y;
    }
    #pragma unroll
    for (int p = 0; p < 4; p++) {
        float2 v = __half22float2(B.h[p]);
        nb[8+2*p]   += wt * v.x;
        nb[8+2*p+1] += wt * v.y;
    }
}

// ---- main fused kernel: one thread = one (i, h, w) output pixel ----
// R8 config (linear row CTAs, egoPart in regs, 3 CTAs/SM) + fp16 LDG.128
// gathers from the pixel-major scratch.
__global__ __launch_bounds__(256, 3) void disco_fused_kernel(
    float* __restrict__ out)         // [L,C,H,W]
{
    const int gid = blockIdx.x * blockDim.x + threadIdx.x;
    const int i   = gid / HW;
    const int pix = gid - i * HW;
    const int h   = pix >> 8;
    const int w   = pix & 255;
    const float fw = (float)w, fh = (float)h;

    // ego channels from packed scratch -> j-invariant half of layer 1
    float egoPart[16];
    {
        float ego[16];
        Pack8 A, B;
        A.u = __ldg(&g_xp[((size_t)i * HW + pix) * 2 + 0]);
        B.u = __ldg(&g_xp[((size_t)i * HW + pix) * 2 + 1]);
        #pragma unroll
        for (int p = 0; p < 4; p++) {
            float2 v = __half22float2(A.h[p]);
            ego[2*p] = v.x; ego[2*p+1] = v.y;
            float2 u = __half22float2(B.h[p]);
            ego[8+2*p] = u.x; ego[8+2*p+1] = u.y;
        }
        #pragma unroll
        for (int o = 0; o < 16; o++) {
            float s = cc.b1[o];
            #pragma unroll
            for (int c = 0; c < 16; c++) s += cc.w1e[o][c] * ego[c];
            egoPart[o] = s;
        }
    }

    // softmax without max-tracking: logits are ReLU'd (>=0, small) -> no overflow.
    float ssum = 0.0f;
    float acc[16];
    #pragma unroll
    for (int c = 0; c < 16; c++) acc[c] = 0.0f;

    #pragma unroll 1
    for (int j = 0; j < LN; j++) {
        // source coords via inv(T[j][i])
        const int mi = j * 5 + i;
        float sx = cc.minv[mi][0]*fw + cc.minv[mi][1]*fh + cc.minv[mi][2];
        float sy = cc.minv[mi][3]*fw + cc.minv[mi][4]*fh + cc.minv[mi][5];
        float x0f = floorf(sx), y0f = floorf(sy);
        float wx = sx - x0f,    wy = sy - y0f;
        bool vx0 = (x0f >=  0.0f) && (x0f <= 255.0f);
        bool vx1 = (x0f >= -1.0f) && (x0f <= 254.0f);
        bool vy0 = (y0f >=  0.0f) && (y0f <= 255.0f);
        bool vy1 = (y0f >= -1.0f) && (y0f <= 254.0f);
        float w00 = (vx0 && vy0) ? (1.0f - wx) * (1.0f - wy) : 0.0f;
        float w01 = (vx1 && vy0) ? wx * (1.0f - wy) : 0.0f;
        float w10 = (vx0 && vy1) ? (1.0f - wx) * wy : 0.0f;
        float w11 = (vx1 && vy1) ? wx * wy : 0.0f;
        int ix0 = (int)x0f, iy0 = (int)y0f;
        int cx0 = min(max(ix0,     0), 255);
        int cx1 = min(max(ix0 + 1, 0), 255);
        int cy0 = min(max(iy0,     0), 255);
        int cy1 = min(max(iy0 + 1, 0), 255);
        int o00 = cy0 * WN + cx0, o01 = cy0 * WN + cx1;
        int o10 = cy1 * WN + cx0, o11 = cy1 * WN + cx1;

        // bilinear sample: 4 taps x 2 LDG.128 from pixel-major fp16 scratch
        float nb[16];
        #pragma unroll
        for (int c = 0; c < 16; c++) nb[c] = 0.0f;
        const uint4* xp = g_xp + (size_t)j * HW * 2;
        tap_accum(xp, o00, w00, nb);
        tap_accum(xp, o01, w01, nb);
        tap_accum(xp, o10, w10, nb);
        tap_accum(xp, o11, w11, nb);

        // MLP: 32->16->8->4->1 (ego half of layer 1 precomputed)
        float h1[16];
        #pragma unroll
        for (int o = 0; o < 16; o++) {
            float s = egoPart[o];
            #pragma unroll
            for (int c = 0; c < 16; c++) s += cc.w1n[o][c] * nb[c];
            h1[o] = fmaxf(s, 0.0f);
        }
        float h2[8];
        #pragma unroll
        for (int o = 0; o < 8; o++) {
            float s = cc.b2[o];
            #pragma unroll
            for (int c = 0; c < 16; c++) s += cc.w2[o][c] * h1[c];
            h2[o] = fmaxf(s, 0.0f);
        }
        float h3[4];
        #pragma unroll
        for (int o = 0; o < 4; o++) {
            float s = cc.b3[o];
            #pragma unroll
            for (int c = 0; c < 8; c++) s += cc.w3[o][c] * h2[c];
            h3[o] = fmaxf(s, 0.0f);
        }
        float logit = cc.b4;
        #pragma unroll
        for (int c = 0; c < 4; c++) logit += cc.w4[c] * h3[c];
        logit = fmaxf(logit, 0.0f);

        // un-normalized softmax accumulate
        float e = __expf(logit);
        ssum += e;
        #pragma unroll
        for (int c = 0; c < 16; c++) acc[c] += e * nb[c];
    }

    // out = wm @ (acc/ssum) + bm  ->  (wm @ acc) * rinv + bm
    float rinv = 1.0f / ssum;
    float* op = out + (size_t)i * CN * HW + pix;
    #pragma unroll
    for (int o = 0; o < 16; o++) {
        float s = 0.0f;
        #pragma unroll
        for (int c = 0; c < 16; c++) s += cc.wm[o][c] * acc[c];
        op[o * HW] = s * rinv + cc.bm[o];
    }
}

extern "C" void kernel_launch(void* const* d_in, const int* in_sizes, int n_in,
                              void* d_out, int out_size) {
    (void)in_sizes; (void)n_in; (void)out_size;
    // metadata order: x, record_len, pairwise_t_matrix,
    // w1,b1,g1,be1,rm1,rv1, w2,b2,g2,be2,rm2,rv2, w3,b3,g3,be3,rm3,rv3, w4,b4, wm,bm
    const float* x   = (const float*)d_in[0];
    const float* ptm = (const float*)d_in[2];

    fold_kernel<<<1, 256>>>(
        ptm,
        (const float*)d_in[3],  (const float*)d_in[4],
        (const float*)d_in[5],  (const float*)d_in[6],
        (const float*)d_in[7],  (const float*)d_in[8],
        (const float*)d_in[9],  (const float*)d_in[10],
        (const float*)d_in[11], (const float*)d_in[12],
        (const float*)d_in[13], (const float*)d_in[14],
        (const float*)d_in[15], (const float*)d_in[16],
        (const float*)d_in[17], (const float*)d_in[18],
        (const float*)d_in[19], (const float*)d_in[20],
        (const float*)d_in[21], (const float*)d_in[22],
        (const float*)d_in[23], (const float*)d_in[24]);

    // stage -> constant bank (graph-capturable D2D memcpy node)
    void* foldAddr = nullptr;
    cudaGetSymbolAddress(&foldAddr, g_fold);
    cudaMemcpyToSymbolAsync(cc, foldAddr, sizeof(Consts), 0,
                            cudaMemcpyDeviceToDevice, 0);

    const int total = LN * HW;          // 327680
    const int threads = 256;
    const int blocks = (total + threads - 1) / threads;   // 1280

    repack_kernel<<<blocks, threads>>>(x);
    disco_fused_kernel<<<blocks, threads>>>((float*)d_out);
}

// round 16
// speedup vs baseline: 1.1601x; 1.0439x over previous
#include <cuda_runtime.h>
#include <cuda_fp16.h>
#include <cuda_bf16.h>

#define LN 5
#define CN 16
#define HN 256
#define WN 256
#define HW (HN*WN)
#define BN_EPS 1e-5f
#define INV_RATIO 1.25f   /* 1 / (0.4 * 2) */

// All loop-invariant parameters live in the constant bank -> LDCU/uniform port.
struct Consts {
    float minv[25][6];     // inverse affines, scaled translations
    float w1n[16][16];     // layer1, nb half (BN-folded)
    float w1e[16][16];     // layer1, ego half (BN-folded)
    float b1[16];
    float w2[8][16];  float b2[8];
    float w3[4][8];   float b3[4];
    float w4[4];      float b4;
    float wm[16][16]; float bm[16];
};

__constant__ Consts cc;      // read by the main kernel
__device__   Consts g_fold;  // staging: written by prologue, memcpy'd to cc

// fp16 pixel-major repack of x: [L, H, W, C] as 2x uint4 (8 halves each) per
// pixel. One bilinear tap = 2 LDG.128 instead of 16 scattered LDG.32, and a
// 128B line covers 4 source pixels -> ~4x fewer l1tex wavefronts on gathers.
__device__ uint4 g_xp[(size_t)LN * HW * 2];   // 10.5 MB scratch

union Pack8 { uint4 u; __half2 h[4]; };

// ---- merged prologue: blocks 0..1279 repack x; block 1280 does the BN-fold
// and affine inversions. The fold block's serial-load latency hides behind
// the repack wave instead of costing its own ~10us launch.
__global__ __launch_bounds__(256) void prologue_kernel(
    const float* __restrict__ x,
    const float* __restrict__ ptm,
    const float* __restrict__ w1, const float* __restrict__ b1,
    const float* __restrict__ g1, const float* __restrict__ be1,
    const float* __restrict__ rm1, const float* __restrict__ rv1,
    const float* __restrict__ w2, const float* __restrict__ b2,
    const float* __restrict__ g2, const float* __restrict__ be2,
    const float* __restrict__ rm2, const float* __restrict__ rv2,
    const float* __restrict__ w3, const float* __restrict__ b3,
    const float* __restrict__ g3, const float* __restrict__ be3,
    const float* __restrict__ rm3, const float* __restrict__ rv3,
    const float* __restrict__ w4, const float* __restrict__ b4,
    const float* __restrict__ wm, const float* __restrict__ bm)
{
    const int tid = threadIdx.x;

    if (blockIdx.x < (LN * HW) / 256) {
        // ---- repack: channel-major f32 -> pixel-major fp16 ----
        const int gid = blockIdx.x * 256 + tid;
        const int l   = gid / HW;
        const int pix = gid - l * HW;
        const float* xi = x + (size_t)l * CN * HW + pix;

        Pack8 a, b;
        #pragma unroll
        for (int p = 0; p < 4; p++)
            a.h[p] = __floats2half2_rn(__ldg(xi + (2*p) * HW), __ldg(xi + (2*p+1) * HW));
        #pragma unroll
        for (int p = 0; p < 4; p++)
            b.h[p] = __floats2half2_rn(__ldg(xi + (8+2*p) * HW), __ldg(xi + (8+2*p+1) * HW));

        g_xp[(size_t)gid * 2 + 0] = a.u;
        g_xp[(size_t)gid * 2 + 1] = b.u;
        return;
    }

    // ---- fold block ----
    for (int idx = tid; idx < 16*32; idx += 256) {
        int o = idx >> 5, c = idx & 31;
        float v = w1[idx] * (g1[o] * rsqrtf(rv1[o] + BN_EPS));
        if (c < 16) g_fold.w1n[o][c]      = v;
        else        g_fold.w1e[o][c - 16] = v;
    }
    for (int idx = tid; idx < 8*16; idx += 256) {
        int o = idx >> 4;
        g_fold.w2[o][idx & 15] = w2[idx] * (g2[o] * rsqrtf(rv2[o] + BN_EPS));
    }
    for (int idx = tid; idx < 4*8; idx += 256) {
        int o = idx >> 3;
        g_fold.w3[o][idx & 7] = w3[idx] * (g3[o] * rsqrtf(rv3[o] + BN_EPS));
    }
    for (int idx = tid; idx < 16*16; idx += 256)
        g_fold.wm[idx >> 4][idx & 15] = wm[idx];

    if (tid < 16) {
        float sc = g1[tid] * rsqrtf(rv1[tid] + BN_EPS);
        g_fold.b1[tid] = (b1[tid] - rm1[tid]) * sc + be1[tid];
        g_fold.bm[tid] = bm[tid];
    }
    if (tid < 8) {
        float sc = g2[tid] * rsqrtf(rv2[tid] + BN_EPS);
        g_fold.b2[tid] = (b2[tid] - rm2[tid]) * sc + be2[tid];
    }
    if (tid < 4) {
        float sc = g3[tid] * rsqrtf(rv3[tid] + BN_EPS);
        g_fold.b3[tid] = (b3[tid] - rm3[tid]) * sc + be3[tid];
        g_fold.w4[tid] = w4[tid];
    }
    if (tid == 0) g_fold.b4 = b4[0];

    // analytic inverse of [[a,b,tx],[c,d,ty],[0,0,1]] for all 25 (j,i) pairs
    if (tid >= 32 && tid < 32 + 25) {
        const int k = tid - 32;
        const float* m = ptm + k * 16;
        float a = m[0], b = m[1], tx = m[3] * INV_RATIO;
        float c = m[4], d = m[5], ty = m[7] * INV_RATIO;
        float inv = 1.0f / (a*d - b*c);
        g_fold.minv[k][0] =  d * inv;
        g_fold.minv[k][1] = -b * inv;
        g_fold.minv[k][2] = (b*ty - d*tx) * inv;
        g_fold.minv[k][3] = -c * inv;
        g_fold.minv[k][4] =  a * inv;
        g_fold.minv[k][5] = (c*tx - a*ty) * inv;
    }
}

__device__ __forceinline__ void tap_accum(const uint4* __restrict__ xp,
                                          int off, float wt, float* nb)
{
    Pack8 A, B;
    A.u = __ldg(xp + ((size_t)off << 1));
    B.u = __ldg(xp + ((size_t)off << 1) + 1);
    #pragma unroll
    for (int p = 0; p < 4; p++) {
        float2 v = __half22float2(A.h[p]);
        nb[2*p]   += wt * v.x;
        nb[2*p+1] += wt * v.y;
    }
    #pragma unroll
    for (int p = 0; p < 4; p++) {
        float2 v = __half22float2(B.h[p]);
        nb[8+2*p]   += wt * v.x;
        nb[8+2*p+1] += wt * v.y;
    }
}

// ---- main fused kernel: one thread = one (i, h, w) output pixel ----
// grid (256, 5): blockIdx.y = agent i (no division; mi block-uniform),
// blockIdx.x covers pixels. R8 config otherwise + fp16 LDG.128 gathers.
__global__ __launch_bounds__(256, 3) void disco_fused_kernel(
    float* __restrict__ out)         // [L,C,H,W]
{
    const int i   = blockIdx.y;
    const int pix = blockIdx.x * 256 + threadIdx.x;
    const int h   = pix >> 8;
    const int w   = pix & 255;
    const float fw = (float)w, fh = (float)h;

    // ego channels from packed scratch -> j-invariant half of layer 1
    float egoPart[16];
    {
        float ego[16];
        Pack8 A, B;
        A.u = __ldg(&g_xp[((size_t)i * HW + pix) * 2 + 0]);
        B.u = __ldg(&g_xp[((size_t)i * HW + pix) * 2 + 1]);
        #pragma unroll
        for (int p = 0; p < 4; p++) {
            float2 v = __half22float2(A.h[p]);
            ego[2*p] = v.x; ego[2*p+1] = v.y;
            float2 u = __half22float2(B.h[p]);
            ego[8+2*p] = u.x; ego[8+2*p+1] = u.y;
        }
        #pragma unroll
        for (int o = 0; o < 16; o++) {
            float s = cc.b1[o];
            #pragma unroll
            for (int c = 0; c < 16; c++) s += cc.w1e[o][c] * ego[c];
            egoPart[o] = s;
        }
    }

    // softmax without max-tracking: logits are ReLU'd (>=0, small) -> no overflow.
    float ssum = 0.0f;
    float acc[16];
    #pragma unroll
    for (int c = 0; c < 16; c++) acc[c] = 0.0f;

    #pragma unroll 1
    for (int j = 0; j < LN; j++) {
        // source coords via inv(T[j][i]); mi is block-uniform -> LDCU
        const int mi = j * 5 + i;
        float sx = cc.minv[mi][0]*fw + cc.minv[mi][1]*fh + cc.minv[mi][2];
        float sy = cc.minv[mi][3]*fw + cc.minv[mi][4]*fh + cc.minv[mi][5];
        float x0f = floorf(sx), y0f = floorf(sy);
        float wx = sx - x0f,    wy = sy - y0f;
        bool vx0 = (x0f >=  0.0f) && (x0f <= 255.0f);
        bool vx1 = (x0f >= -1.0f) && (x0f <= 254.0f);
        bool vy0 = (y0f >=  0.0f) && (y0f <= 255.0f);
        bool vy1 = (y0f >= -1.0f) && (y0f <= 254.0f);
        float w00 = (vx0 && vy0) ? (1.0f - wx) * (1.0f - wy) : 0.0f;
        float w01 = (vx1 && vy0) ? wx * (1.0f - wy) : 0.0f;
        float w10 = (vx0 && vy1) ? (1.0f - wx) * wy : 0.0f;
        float w11 = (vx1 && vy1) ? wx * wy : 0.0f;
        int ix0 = (int)x0f, iy0 = (int)y0f;
        int cx0 = min(max(ix0,     0), 255);
        int cx1 = min(max(ix0 + 1, 0), 255);
        int cy0 = min(max(iy0,     0), 255);
        int cy1 = min(max(iy0 + 1, 0), 255);
        int o00 = cy0 * WN + cx0, o01 = cy0 * WN + cx1;
        int o10 = cy1 * WN + cx0, o11 = cy1 * WN + cx1;

        // bilinear sample: 4 taps x 2 LDG.128 from pixel-major fp16 scratch
        float nb[16];
        #pragma unroll
        for (int c = 0; c < 16; c++) nb[c] = 0.0f;
        const uint4* xp = g_xp + (size_t)j * HW * 2;
        tap_accum(xp, o00, w00, nb);
        tap_accum(xp, o01, w01, nb);
        tap_accum(xp, o10, w10, nb);
        tap_accum(xp, o11, w11, nb);

        // MLP: 32->16->8->4->1 (ego half of layer 1 precomputed)
        float h1[16];
        #pragma unroll
        for (int o = 0; o < 16; o++) {
            float s = egoPart[o];
            #pragma unroll
            for (int c = 0; c < 16; c++) s += cc.w1n[o][c] * nb[c];
            h1[o] = fmaxf(s, 0.0f);
        }
        float h2[8];
        #pragma unroll
        for (int o = 0; o < 8; o++) {
            float s = cc.b2[o];
            #pragma unroll
            for (int c = 0; c < 16; c++) s += cc.w2[o][c] * h1[c];
            h2[o] = fmaxf(s, 0.0f);
        }
        float h3[4];
        #pragma unroll
        for (int o = 0; o < 4; o++) {
            float s = cc.b3[o];
            #pragma unroll
            for (int c = 0; c < 8; c++) s += cc.w3[o][c] * h2[c];
            h3[o] = fmaxf(s, 0.0f);
        }
        float logit = cc.b4;
        #pragma unroll
        for (int c = 0; c < 4; c++) logit += cc.w4[c] * h3[c];
        logit = fmaxf(logit, 0.0f);

        // un-normalized softmax accumulate
        float e = __expf(logit);
        ssum += e;
        #pragma unroll
        for (int c = 0; c < 16; c++) acc[c] += e * nb[c];
    }

    // out = wm @ (acc/ssum) + bm  ->  (wm @ acc) * rinv + bm
    float rinv = 1.0f / ssum;
    float* op = out + (size_t)i * CN * HW + pix;
    #pragma unroll
    for (int o = 0; o < 16; o++) {
        float s = 0.0f;
        #pragma unroll
        for (int c = 0; c < 16; c++) s += cc.wm[o][c] * acc[c];
        op[o * HW] = s * rinv + cc.bm[o];
    }
}

extern "C" void kernel_launch(void* const* d_in, const int* in_sizes, int n_in,
                              void* d_out, int out_size) {
    (void)in_sizes; (void)n_in; (void)out_size;
    // metadata order: x, record_len, pairwise_t_matrix,
    // w1,b1,g1,be1,rm1,rv1, w2,b2,g2,be2,rm2,rv2, w3,b3,g3,be3,rm3,rv3, w4,b4, wm,bm
    const float* x   = (const float*)d_in[0];
    const float* ptm = (const float*)d_in[2];

    // merged repack + fold: 1280 repack blocks + 1 fold block
    prologue_kernel<<<(LN * HW) / 256 + 1, 256>>>(
        x, ptm,
        (const float*)d_in[3],  (const float*)d_in[4],
        (const float*)d_in[5],  (const float*)d_in[6],
        (const float*)d_in[7],  (const float*)d_in[8],
        (const float*)d_in[9],  (const float*)d_in[10],
        (const float*)d_in[11], (const float*)d_in[12],
        (const float*)d_in[13], (const float*)d_in[14],
        (const float*)d_in[15], (const float*)d_in[16],
        (const float*)d_in[17], (const float*)d_in[18],
        (const float*)d_in[19], (const float*)d_in[20],
        (const float*)d_in[21], (const float*)d_in[22],
        (const float*)d_in[23], (const float*)d_in[24]);

    // stage -> constant bank (graph-capturable D2D memcpy node)
    void* foldAddr = nullptr;
    cudaGetSymbolAddress(&foldAddr, g_fold);
    cudaMemcpyToSymbolAsync(cc, foldAddr, sizeof(Consts), 0,
                            cudaMemcpyDeviceToDevice, 0);

    dim3 grid(HW / 256, LN);   // (256, 5)
    disco_fused_kernel<<<grid, 256>>>((float*)d_out);
}

// round 17
// speedup vs baseline: 1.2301x; 1.0603x over previous
#include <cuda_runtime.h>
#include <cuda_fp16.h>
#include <cuda_bf16.h>

#define LN 5
#define CN 16
#define HN 256
#define WN 256
#define HW (HN*WN)
#define BN_EPS 1e-5f
#define INV_RATIO 1.25f   /* 1 / (0.4 * 2) */

// All loop-invariant parameters live in the constant bank -> LDCU/uniform port.
struct Consts {
    float minv[25][6];     // inverse affines, scaled translations
    float w1n[16][16];     // layer1, nb half (BN-folded)
    float w1e[16][16];     // layer1, ego half (BN-folded)
    float b1[16];
    float w2[8][16];  float b2[8];
    float w3[4][8];   float b3[4];
    float w4[4];      float b4;
    float wm[16][16]; float bm[16];
};

__constant__ Consts cc;      // read by the main kernel
__device__   Consts g_fold;  // staging: written by prologue, memcpy'd to cc

// fp16 pixel-major repack of x: [L, H, W, C] as 2x uint4 (8 halves each) per
// pixel. One bilinear tap = 2 LDG.128; taps accumulate in half2 via HFMA2.
__device__ uint4 g_xp[(size_t)LN * HW * 2];   // 10.5 MB scratch

union Pack8 { uint4 u; __half2 h[4]; };

// ---- merged prologue: blocks 0..1279 repack x; block 1280 does the BN-fold
// and affine inversions (its serial-load latency hides behind the repack wave).
__global__ __launch_bounds__(256) void prologue_kernel(
    const float* __restrict__ x,
    const float* __restrict__ ptm,
    const float* __restrict__ w1, const float* __restrict__ b1,
    const float* __restrict__ g1, const float* __restrict__ be1,
    const float* __restrict__ rm1, const float* __restrict__ rv1,
    const float* __restrict__ w2, const float* __restrict__ b2,
    const float* __restrict__ g2, const float* __restrict__ be2,
    const float* __restrict__ rm2, const float* __restrict__ rv2,
    const float* __restrict__ w3, const float* __restrict__ b3,
    const float* __restrict__ g3, const float* __restrict__ be3,
    const float* __restrict__ rm3, const float* __restrict__ rv3,
    const float* __restrict__ w4, const float* __restrict__ b4,
    const float* __restrict__ wm, const float* __restrict__ bm)
{
    const int tid = threadIdx.x;

    if (blockIdx.x < (LN * HW) / 256) {
        // ---- repack: channel-major f32 -> pixel-major fp16 ----
        const int gid = blockIdx.x * 256 + tid;
        const int l   = gid / HW;
        const int pix = gid - l * HW;
        const float* xi = x + (size_t)l * CN * HW + pix;

        Pack8 a, b;
        #pragma unroll
        for (int p = 0; p < 4; p++)
            a.h[p] = __floats2half2_rn(__ldg(xi + (2*p) * HW), __ldg(xi + (2*p+1) * HW));
        #pragma unroll
        for (int p = 0; p < 4; p++)
            b.h[p] = __floats2half2_rn(__ldg(xi + (8+2*p) * HW), __ldg(xi + (8+2*p+1) * HW));

        g_xp[(size_t)gid * 2 + 0] = a.u;
        g_xp[(size_t)gid * 2 + 1] = b.u;
        return;
    }

    // ---- fold block ----
    for (int idx = tid; idx < 16*32; idx += 256) {
        int o = idx >> 5, c = idx & 31;
        float v = w1[idx] * (g1[o] * rsqrtf(rv1[o] + BN_EPS));
        if (c < 16) g_fold.w1n[o][c]      = v;
        else        g_fold.w1e[o][c - 16] = v;
    }
    for (int idx = tid; idx < 8*16; idx += 256) {
        int o = idx >> 4;
        g_fold.w2[o][idx & 15] = w2[idx] * (g2[o] * rsqrtf(rv2[o] + BN_EPS));
    }
    for (int idx = tid; idx < 4*8; idx += 256) {
        int o = idx >> 3;
        g_fold.w3[o][idx & 7] = w3[idx] * (g3[o] * rsqrtf(rv3[o] + BN_EPS));
    }
    for (int idx = tid; idx < 16*16; idx += 256)
        g_fold.wm[idx >> 4][idx & 15] = wm[idx];

    if (tid < 16) {
        float sc = g1[tid] * rsqrtf(rv1[tid] + BN_EPS);
        g_fold.b1[tid] = (b1[tid] - rm1[tid]) * sc + be1[tid];
        g_fold.bm[tid] = bm[tid];
    }
    if (tid < 8) {
        float sc = g2[tid] * rsqrtf(rv2[tid] + BN_EPS);
        g_fold.b2[tid] = (b2[tid] - rm2[tid]) * sc + be2[tid];
    }
    if (tid < 4) {
        float sc = g3[tid] * rsqrtf(rv3[tid] + BN_EPS);
        g_fold.b3[tid] = (b3[tid] - rm3[tid]) * sc + be3[tid];
        g_fold.w4[tid] = w4[tid];
    }
    if (tid == 0) g_fold.b4 = b4[0];

    // analytic inverse of [[a,b,tx],[c,d,ty],[0,0,1]] for all 25 (j,i) pairs
    if (tid >= 32 && tid < 32 + 25) {
        const int k = tid - 32;
        const float* m = ptm + k * 16;
        float a = m[0], b = m[1], tx = m[3] * INV_RATIO;
        float c = m[4], d = m[5], ty = m[7] * INV_RATIO;
        float inv = 1.0f / (a*d - b*c);
        g_fold.minv[k][0] =  d * inv;
        g_fold.minv[k][1] = -b * inv;
        g_fold.minv[k][2] = (b*ty - d*tx) * inv;
        g_fold.minv[k][3] = -c * inv;
        g_fold.minv[k][4] =  a * inv;
        g_fold.minv[k][5] = (c*tx - a*ty) * inv;
    }
}

// one bilinear tap accumulated in half2 (HFMA2, full-rate, 1-reg operands)
__device__ __forceinline__ void tap_h2(const uint4* __restrict__ xp,
                                       int off, __half2 wt, __half2* nbh)
{
    Pack8 A, B;
    A.u = __ldg(xp + ((size_t)off << 1));
    B.u = __ldg(xp + ((size_t)off << 1) + 1);
    #pragma unroll
    for (int p = 0; p < 4; p++) nbh[p]   = __hfma2(wt, A.h[p], nbh[p]);
    #pragma unroll
    for (int p = 0; p < 4; p++) nbh[4+p] = __hfma2(wt, B.h[p], nbh[4+p]);
}

// ---- main fused kernel: one thread = one (i, h, w) output pixel ----
// grid (256, 5): blockIdx.y = agent i (block-uniform minv), R8 occupancy
// config, fp16 LDG.128 gathers + half2 tap accumulation.
__global__ __launch_bounds__(256, 3) void disco_fused_kernel(
    float* __restrict__ out)         // [L,C,H,W]
{
    const int i   = blockIdx.y;
    const int pix = blockIdx.x * 256 + threadIdx.x;
    const int h   = pix >> 8;
    const int w   = pix & 255;
    const float fw = (float)w, fh = (float)h;

    // ego channels from packed scratch -> j-invariant half of layer 1
    float egoPart[16];
    {
        float ego[16];
        Pack8 A, B;
        A.u = __ldg(&g_xp[((size_t)i * HW + pix) * 2 + 0]);
        B.u = __ldg(&g_xp[((size_t)i * HW + pix) * 2 + 1]);
        #pragma unroll
        for (int p = 0; p < 4; p++) {
            float2 v = __half22float2(A.h[p]);
            ego[2*p] = v.x; ego[2*p+1] = v.y;
            float2 u = __half22float2(B.h[p]);
            ego[8+2*p] = u.x; ego[8+2*p+1] = u.y;
        }
        #pragma unroll
        for (int o = 0; o < 16; o++) {
            float s = cc.b1[o];
            #pragma unroll
            for (int c = 0; c < 16; c++) s += cc.w1e[o][c] * ego[c];
            egoPart[o] = s;
        }
    }

    // softmax without max-tracking: logits are ReLU'd (>=0, small) -> no overflow.
    float ssum = 0.0f;
    float acc[16];
    #pragma unroll
    for (int c = 0; c < 16; c++) acc[c] = 0.0f;

    #pragma unroll 1
    for (int j = 0; j < LN; j++) {
        // source coords via inv(T[j][i]); mi is block-uniform -> LDCU
        const int mi = j * 5 + i;
        float sx = cc.minv[mi][0]*fw + cc.minv[mi][1]*fh + cc.minv[mi][2];
        float sy = cc.minv[mi][3]*fw + cc.minv[mi][4]*fh + cc.minv[mi][5];
        float x0f = floorf(sx), y0f = floorf(sy);
        float wx = sx - x0f,    wy = sy - y0f;
        bool vx0 = (x0f >=  0.0f) && (x0f <= 255.0f);
        bool vx1 = (x0f >= -1.0f) && (x0f <= 254.0f);
        bool vy0 = (y0f >=  0.0f) && (y0f <= 255.0f);
        bool vy1 = (y0f >= -1.0f) && (y0f <= 254.0f);
        float w00 = (vx0 && vy0) ? (1.0f - wx) * (1.0f - wy) : 0.0f;
        float w01 = (vx1 && vy0) ? wx * (1.0f - wy) : 0.0f;
        float w10 = (vx0 && vy1) ? (1.0f - wx) * wy : 0.0f;
        float w11 = (vx1 && vy1) ? wx * wy : 0.0f;
        int ix0 = (int)x0f, iy0 = (int)y0f;
        int cx0 = min(max(ix0,     0), 255);
        int cx1 = min(max(ix0 + 1, 0), 255);
        int cy0 = min(max(iy0,     0), 255);
        int cy1 = min(max(iy0 + 1, 0), 255);
        int o00 = cy0 * WN + cx0, o01 = cy0 * WN + cx1;
        int o10 = cy1 * WN + cx0, o11 = cy1 * WN + cx1;

        // bilinear sample: 4 taps x 2 LDG.128, accumulated in half2 (HFMA2)
        __half2 nbh[8];
        #pragma unroll
        for (int p = 0; p < 8; p++) nbh[p] = __float2half2_rn(0.0f);
        const uint4* xp = g_xp + (size_t)j * HW * 2;
        tap_h2(xp, o00, __float2half2_rn(w00), nbh);
        tap_h2(xp, o01, __float2half2_rn(w01), nbh);
        tap_h2(xp, o10, __float2half2_rn(w10), nbh);
        tap_h2(xp, o11, __float2half2_rn(w11), nbh);

        // widen once to fp32 for the MLP + softmax-weighted accumulation
        float nb[16];
        #pragma unroll
        for (int p = 0; p < 8; p++) {
            float2 v = __half22float2(nbh[p]);
            nb[2*p] = v.x; nb[2*p+1] = v.y;
        }

        // MLP: 32->16->8->4->1 (ego half of layer 1 precomputed), all fp32
        float h1[16];
        #pragma unroll
        for (int o = 0; o < 16; o++) {
            float s = egoPart[o];
            #pragma unroll
            for (int c = 0; c < 16; c++) s += cc.w1n[o][c] * nb[c];
            h1[o] = fmaxf(s, 0.0f);
        }
        float h2[8];
        #pragma unroll
        for (int o = 0; o < 8; o++) {
            float s = cc.b2[o];
            #pragma unroll
            for (int c = 0; c < 16; c++) s += cc.w2[o][c] * h1[c];
            h2[o] = fmaxf(s, 0.0f);
        }
        float h3[4];
        #pragma unroll
        for (int o = 0; o < 4; o++) {
            float s = cc.b3[o];
            #pragma unroll
            for (int c = 0; c < 8; c++) s += cc.w3[o][c] * h2[c];
            h3[o] = fmaxf(s, 0.0f);
        }
        float logit = cc.b4;
        #pragma unroll
        for (int c = 0; c < 4; c++) logit += cc.w4[c] * h3[c];
        logit = fmaxf(logit, 0.0f);

        // un-normalized softmax accumulate
        float e = __expf(logit);
        ssum += e;
        #pragma unroll
        for (int c = 0; c < 16; c++) acc[c] += e * nb[c];
    }

    // out = wm @ (acc/ssum) + bm  ->  (wm @ acc) * rinv + bm
    float rinv = 1.0f / ssum;
    float* op = out + (size_t)i * CN * HW + pix;
    #pragma unroll
    for (int o = 0; o < 16; o++) {
        float s = 0.0f;
        #pragma unroll
        for (int c = 0; c < 16; c++) s += cc.wm[o][c] * acc[c];
        op[o * HW] = s * rinv + cc.bm[o];
    }
}

extern "C" void kernel_launch(void* const* d_in, const int* in_sizes, int n_in,
                              void* d_out, int out_size) {
    (void)in_sizes; (void)n_in; (void)out_size;
    // metadata order: x, record_len, pairwise_t_matrix,
    // w1,b1,g1,be1,rm1,rv1, w2,b2,g2,be2,rm2,rv2, w3,b3,g3,be3,rm3,rv3, w4,b4, wm,bm
    const float* x   = (const float*)d_in[0];
    const float* ptm = (const float*)d_in[2];

    // merged repack + fold: 1280 repack blocks + 1 fold block
    prologue_kernel<<<(LN * HW) / 256 + 1, 256>>>(
        x, ptm,
        (const float*)d_in[3],  (const float*)d_in[4],
        (const float*)d_in[5],  (const float*)d_in[6],
        (const float*)d_in[7],  (const float*)d_in[8],
        (const float*)d_in[9],  (const float*)d_in[10],
        (const float*)d_in[11], (const float*)d_in[12],
        (const float*)d_in[13], (const float*)d_in[14],
        (const float*)d_in[15], (const float*)d_in[16],
        (const float*)d_in[17], (const float*)d_in[18],
        (const float*)d_in[19], (const float*)d_in[20],
        (const float*)d_in[21], (const float*)d_in[22],
        (const float*)d_in[23], (const float*)d_in[24]);

    // stage -> constant bank (graph-capturable D2D memcpy node)
    void* foldAddr = nullptr;
    cudaGetSymbolAddress(&foldAddr, g_fold);
    cudaMemcpyToSymbolAsync(cc, foldAddr, sizeof(Consts), 0,
                            cudaMemcpyDeviceToDevice, 0);

    dim3 grid(HW / 256, LN);   // (256, 5)
    disco_fused_kernel<<<grid, 256>>>((float*)d_out);
}